// round 13
// baseline (speedup 1.0000x reference)
#include <cuda_runtime.h>
#include <cstdint>

// Problem constants
#define BB   64
#define TT   2048
#define II   200
#define HH   100
#define G4   400   // 4*H
#define HP   104   // padded h length (pad = 0)

// Scratch: xg[t][b][j] (t-major so scan CTA b streams coalesced rows), ~210MB.
__device__ float g_xg[(size_t)TT * BB * G4];

// ---- packed fp32x2 helpers ---------------------------------------------
union f2u { float2 f; unsigned long long u; };
union f4u { float4 f; ulonglong2 u; };

__device__ __forceinline__ unsigned long long ffma2(unsigned long long a,
                                                    unsigned long long b,
                                                    unsigned long long c) {
    unsigned long long d;
    asm("fma.rn.f32x2 %0, %1, %2, %3;" : "=l"(d) : "l"(a), "l"(b), "l"(c));
    return d;
}
__device__ __forceinline__ unsigned long long fadd2(unsigned long long a,
                                                    unsigned long long b) {
    unsigned long long d;
    asm("add.rn.f32x2 %0, %1, %2;" : "=l"(d) : "l"(a), "l"(b));
    return d;
}
__device__ __forceinline__ float tanh_mufu(float x) {
    float t;
    asm("tanh.approx.f32 %0, %1;" : "=f"(t) : "f"(x));
    return t;
}

// ---- kernel 1: input projection (register-blocked SIMT GEMM) -----------
// C[131072, 400] = x[131072, 200] @ W_ih^T  (+bias) -> g_xg[t][b][col]
// CTA tile: 64 rows x 100 cols (grid 2048 x 4). 200 threads, thread tile 8x4.
#define KC 20
#define AS_STRIDE 68   // 68*4=272B, 16B aligned

__global__ __launch_bounds__(200, 4)
void proj_kernel(const float* __restrict__ x,
                 const float* __restrict__ Wih,
                 const float* __restrict__ bih,
                 const float* __restrict__ bhh) {
    __shared__ float As[KC * AS_STRIDE];   // As[k][r], 5.44 KB
    __shared__ float Bs[KC * HH];          // Bs[k][jc], 8 KB

    const int tid  = threadIdx.x;
    const int tx   = tid % 25;             // col group: cols tx*4 .. tx*4+3
    const int ty   = tid / 25;             // row group: rows ty*8 .. ty*8+7
    const int row0 = blockIdx.x * 64;
    const int c0   = blockIdx.y * HH;      // global column base (0/100/200/300)

    unsigned long long acc[8][2];
    #pragma unroll
    for (int r = 0; r < 8; ++r) { acc[r][0] = 0ULL; acc[r][1] = 0ULL; }

    for (int cch = 0; cch < II / KC; ++cch) {
        const int k0 = cch * KC;
        __syncthreads();   // previous chunk fully consumed

        // Stage A: 64 rows x 20 k, transposed to As[k][r]. 320 float4 loads.
        for (int idx = tid; idx < 64 * (KC / 4); idx += 200) {
            int r = idx / (KC / 4);
            int q = idx - r * (KC / 4);
            float4 v = *(const float4*)&x[(size_t)(row0 + r) * II + k0 + 4 * q];
            As[(4 * q + 0) * AS_STRIDE + r] = v.x;
            As[(4 * q + 1) * AS_STRIDE + r] = v.y;
            As[(4 * q + 2) * AS_STRIDE + r] = v.z;
            As[(4 * q + 3) * AS_STRIDE + r] = v.w;
        }
        // Stage B (transposing): thread t<100 owns W_ih row j=c0+t (L2-resident)
        if (tid < HH) {
            const float* wrow = &Wih[(size_t)(c0 + tid) * II + k0];
            #pragma unroll
            for (int q = 0; q < KC / 4; ++q) {
                float4 v = *(const float4*)&wrow[4 * q];
                Bs[(4 * q + 0) * HH + tid] = v.x;
                Bs[(4 * q + 1) * HH + tid] = v.y;
                Bs[(4 * q + 2) * HH + tid] = v.z;
                Bs[(4 * q + 3) * HH + tid] = v.w;
            }
        }
        __syncthreads();

        #pragma unroll 4
        for (int k = 0; k < KC; ++k) {
            f4u a0, a1, w0;
            a0.f = *(const float4*)&As[k * AS_STRIDE + ty * 8];
            a1.f = *(const float4*)&As[k * AS_STRIDE + ty * 8 + 4];
            w0.f = *(const float4*)&Bs[k * HH + tx * 4];
            float ar[8] = {a0.f.x, a0.f.y, a0.f.z, a0.f.w,
                           a1.f.x, a1.f.y, a1.f.z, a1.f.w};
            #pragma unroll
            for (int r = 0; r < 8; ++r) {
                f2u av; av.f.x = ar[r]; av.f.y = ar[r];
                acc[r][0] = ffma2(av.u, w0.u.x, acc[r][0]);
                acc[r][1] = ffma2(av.u, w0.u.y, acc[r][1]);
            }
        }
    }

    // Epilogue: add bias, scatter rows to g_xg[t][b][col]
    const int col = c0 + tx * 4;
    f4u bi, bh;
    bi.f = *(const float4*)&bih[col];
    bh.f = *(const float4*)&bhh[col];
    float4 bias = make_float4(bi.f.x + bh.f.x, bi.f.y + bh.f.y,
                              bi.f.z + bh.f.z, bi.f.w + bh.f.w);

    #pragma unroll
    for (int r = 0; r < 8; ++r) {
        int m = row0 + ty * 8 + r;
        int b = m >> 11;           // m / 2048
        int t = m & 2047;
        f2u p0, p1;
        p0.u = acc[r][0]; p1.u = acc[r][1];
        float4 o = make_float4(p0.f.x + bias.x, p0.f.y + bias.y,
                               p1.f.x + bias.z, p1.f.y + bias.w);
        *(float4*)&g_xg[((size_t)t * BB + b) * G4 + col] = o;
    }
}

// ---- kernel 2: sequential LSTM scan (octet k-split, shared h loads) -----
// One CTA per batch row, 400 threads. Octet o = tid>>3 owns hidden units
// u0=2o and u0+1. Within the octet, sub = tid&7: g = sub&3 is the gate,
// hsel = sub>>2 is the k-half. Each thread loads 13 float4 of h (its
// k-half) ONCE and feeds them to BOTH units' dot products (52 FFMA2) —
// SM-wide LDS count halves vs one-unit-per-quad. Halves are merged with
// one shfl_xor(4,w=8) per unit; lanes sub 0-3 then finish unit u0, lanes
// 4-7 finish unit u0+1 (two quad-leaders per octet). h double-buffered,
// padded to 104 (pads & W-pads = 0), ONE barrier/step. xg prefetched 4
// steps ahead. Activations: MUFU.TANH (sigmoid = 0.5*tanh(x/2)+0.5).
#define SG 4   // steps per prefetch group

__global__ __launch_bounds__(400, 1)
void scan_kernel(const float* __restrict__ Whh, float* __restrict__ out) {
    const int b    = blockIdx.x;
    const int tid  = threadIdx.x;
    const int o    = tid >> 3;          // octet 0..49
    const int sub  = tid & 7;
    const int g    = sub & 3;           // gate: 0=i 1=f 2=g 3=o
    const int hsel = sub >> 2;          // k-half: 0 -> h[0:52), 1 -> h[52:104)
    const int u0   = 2 * o;             // first unit of this octet
    const int unit = u0 + hsel;         // unit this thread activates/owns
    const int lane = tid & 31;
    const unsigned omask = 0xFFu << (lane & ~7);   // this octet's lanes
    const unsigned qmask = 0xFu  << (lane & ~3);   // this quad's lanes

    __shared__ __align__(16) float h_sh[2][HP];

    // W_hh half-rows for gate g of units u0 and u0+1 (13 float4 each,
    // zero-padded past col 99).
    f4u wA[13], wB[13];
    {
        const float* rA = Whh + (size_t)(g * HH + u0) * HH;
        const float* rB = Whh + (size_t)(g * HH + u0 + 1) * HH;
        #pragma unroll
        for (int i = 0; i < 13; ++i) {
            float ta[4], tb[4];
            #pragma unroll
            for (int k = 0; k < 4; ++k) {
                int idx = hsel * 52 + 4 * i + k;
                ta[k] = (idx < HH) ? rA[idx] : 0.0f;
                tb[k] = (idx < HH) ? rB[idx] : 0.0f;
            }
            wA[i].f = make_float4(ta[0], ta[1], ta[2], ta[3]);
            wB[i].f = make_float4(tb[0], tb[1], tb[2], tb[3]);
        }
    }

    float c = 0.0f, hval = 0.0f;
    if (tid < HP) { h_sh[0][tid] = 0.0f; h_sh[1][tid] = 0.0f; }
    __syncthreads();

    const float* xg = g_xg + (size_t)b * G4 + (g * HH + unit);
    const size_t ts = (size_t)BB * G4;

    float cur[SG], nxt[SG];
    #pragma unroll
    for (int i = 0; i < SG; ++i) cur[i] = __ldcs(&xg[(size_t)i * ts]);

    int p = 0;
    for (int tg = 0; tg < TT; tg += SG) {
        // issue next group's loads NOW (consumed >= SG steps from now)
        #pragma unroll
        for (int i = 0; i < SG; ++i) {
            int tt = tg + SG + i;
            tt = (tt < TT) ? tt : (TT - 1);
            nxt[i] = __ldcs(&xg[(size_t)tt * ts]);
        }

        #pragma unroll
        for (int i = 0; i < SG; ++i) {
            // 4 independent chains (depth 13): one h load feeds both units
            unsigned long long A0 = 0ULL, A1 = 0ULL, B0 = 0ULL, B1 = 0ULL;
            const float4* hb = (const float4*)(h_sh[p] + hsel * 52);
            #pragma unroll
            for (int q = 0; q < 13; ++q) {
                f4u h4; h4.f = hb[q];            // broadcast LDS.128 (x1)
                A0 = ffma2(wA[q].u.x, h4.u.x, A0);
                A1 = ffma2(wA[q].u.y, h4.u.y, A1);
                B0 = ffma2(wB[q].u.x, h4.u.x, B0);
                B1 = ffma2(wB[q].u.y, h4.u.y, B1);
            }
            f2u sA, sB;
            sA.u = fadd2(A0, A1);
            sB.u = fadd2(B0, B1);
            float pA = sA.f.x + sA.f.y;
            float pB = sB.f.x + sB.f.y;

            // merge k-halves within the octet (lanes differing in bit 2)
            pA += __shfl_xor_sync(omask, pA, 4, 8);
            pB += __shfl_xor_sync(omask, pB, 4, 8);

            // this thread now activates gate g of 'unit'
            float gate = (hsel ? pB : pA) + cur[i];
            bool is_t = (g == 2);
            float xx = is_t ? gate : 0.5f * gate;
            float th = tanh_mufu(xx);
            float a  = is_t ? th : fmaf(0.5f, th, 0.5f);

            // quad combine (lanes sub 0-3 for u0, lanes 4-7 for u0+1)
            float fg = __shfl_down_sync(qmask, a, 1, 4);
            float gg = __shfl_down_sync(qmask, a, 2, 4);
            float og = __shfl_down_sync(qmask, a, 3, 4);
            if (g == 0) {                        // two leaders per octet
                c    = fg * c + a * gg;
                hval = og * tanh_mufu(c);
                h_sh[p ^ 1][unit] = hval;        // write OTHER buffer
            }
            __syncthreads();
            p ^= 1;
        }

        #pragma unroll
        for (int i = 0; i < SG; ++i) cur[i] = nxt[i];
    }

    if (g == 0) out[b * HH + unit] = hval;
}

// ---- launch ------------------------------------------------------------
extern "C" void kernel_launch(void* const* d_in, const int* in_sizes, int n_in,
                              void* d_out, int out_size) {
    const float* x   = (const float*)d_in[0];   // [64,2048,200]
    const float* Wih = (const float*)d_in[1];   // [400,200]
    const float* Whh = (const float*)d_in[2];   // [400,100]
    const float* bih = (const float*)d_in[3];   // [400]
    const float* bhh = (const float*)d_in[4];   // [400]
    float* out = (float*)d_out;                 // [64,100]

    proj_kernel<<<dim3(TT * BB / 64, 4), 200>>>(x, Wih, bih, bhh);
    scan_kernel<<<BB, 400>>>(Whh, out);
}

// round 14
// speedup vs baseline: 1.1762x; 1.1762x over previous
#include <cuda_runtime.h>
#include <cstdint>

// Problem constants
#define BB   64
#define TT   2048
#define II   200
#define HH   100
#define G4   400   // 4*H

// Scratch: xg[t][b][j] (t-major so scan CTA b streams coalesced rows), ~210MB.
__device__ float g_xg[(size_t)TT * BB * G4];

// ---- packed fp32x2 helpers ---------------------------------------------
union f2u { float2 f; unsigned long long u; };
union f4u { float4 f; ulonglong2 u; };

__device__ __forceinline__ unsigned long long ffma2(unsigned long long a,
                                                    unsigned long long b,
                                                    unsigned long long c) {
    unsigned long long d;
    asm("fma.rn.f32x2 %0, %1, %2, %3;" : "=l"(d) : "l"(a), "l"(b), "l"(c));
    return d;
}
__device__ __forceinline__ unsigned long long fadd2(unsigned long long a,
                                                    unsigned long long b) {
    unsigned long long d;
    asm("add.rn.f32x2 %0, %1, %2;" : "=l"(d) : "l"(a), "l"(b));
    return d;
}
__device__ __forceinline__ float tanh_(float x) {
    return __fdividef(2.0f, 1.0f + __expf(-2.0f * x)) - 1.0f;
}

// ---- kernel 1: input projection (register double-buffered staging) -----
// C[131072, 400] = x[131072, 200] @ W_ih^T  (+bias) -> g_xg[t][b][col]
// CTA tile: 64 rows x 100 cols (grid 2048 x 4). 200 threads, thread tile 8x4.
// K chunked by 20; chunk ch+1's global loads are issued into REGISTERS
// before computing chunk ch, so L2/DRAM latency hides under compute.
#define KC 20
#define AS_STRIDE 68   // 68*4=272B, 16B aligned

__global__ __launch_bounds__(200, 4)
void proj_kernel(const float* __restrict__ x,
                 const float* __restrict__ Wih,
                 const float* __restrict__ bih,
                 const float* __restrict__ bhh) {
    __shared__ float As[KC * AS_STRIDE];   // As[k][r], 5.44 KB
    __shared__ float Bs[KC * HH];          // Bs[k][jc], 8 KB

    const int tid  = threadIdx.x;
    const int tx   = tid % 25;             // col group: cols tx*4 .. tx*4+3
    const int ty   = tid / 25;             // row group: rows ty*8 .. ty*8+7
    const int row0 = blockIdx.x * 64;
    const int c0   = blockIdx.y * HH;      // global column base (0/100/200/300)

    // A staging ownership: f4 index idx = tid + 200*e (e=0,1), idx < 320
    //   r = idx/5 (row 0..63), q = idx%5 (k-subgroup of 4)
    // B staging ownership: tid < 100 owns W_ih row c0+tid, 5 f4 per chunk.
    const int idxA0 = tid;
    const int idxA1 = tid + 200;           // valid iff tid < 120
    const int rA0 = idxA0 / 5, qA0 = idxA0 - 5 * rA0;
    const int rA1 = idxA1 / 5, qA1 = idxA1 - 5 * rA1;

    f4u aReg[2], bReg[5];

    // preload chunk 0
    {
        aReg[0].f = *(const float4*)&x[(size_t)(row0 + rA0) * II + 4 * qA0];
        if (tid < 120)
            aReg[1].f = *(const float4*)&x[(size_t)(row0 + rA1) * II + 4 * qA1];
        if (tid < HH) {
            const float* wrow = &Wih[(size_t)(c0 + tid) * II];
            #pragma unroll
            for (int q = 0; q < 5; ++q) bReg[q].f = *(const float4*)&wrow[4 * q];
        }
    }

    unsigned long long acc[8][2];
    #pragma unroll
    for (int r = 0; r < 8; ++r) { acc[r][0] = 0ULL; acc[r][1] = 0ULL; }

    for (int cch = 0; cch < II / KC; ++cch) {
        __syncthreads();   // previous chunk fully consumed

        // STS: regs -> smem (transposing)
        {
            float4 v = aReg[0].f;
            As[(4 * qA0 + 0) * AS_STRIDE + rA0] = v.x;
            As[(4 * qA0 + 1) * AS_STRIDE + rA0] = v.y;
            As[(4 * qA0 + 2) * AS_STRIDE + rA0] = v.z;
            As[(4 * qA0 + 3) * AS_STRIDE + rA0] = v.w;
            if (tid < 120) {
                float4 w = aReg[1].f;
                As[(4 * qA1 + 0) * AS_STRIDE + rA1] = w.x;
                As[(4 * qA1 + 1) * AS_STRIDE + rA1] = w.y;
                As[(4 * qA1 + 2) * AS_STRIDE + rA1] = w.z;
                As[(4 * qA1 + 3) * AS_STRIDE + rA1] = w.w;
            }
            if (tid < HH) {
                #pragma unroll
                for (int q = 0; q < 5; ++q) {
                    float4 u = bReg[q].f;
                    Bs[(4 * q + 0) * HH + tid] = u.x;
                    Bs[(4 * q + 1) * HH + tid] = u.y;
                    Bs[(4 * q + 2) * HH + tid] = u.z;
                    Bs[(4 * q + 3) * HH + tid] = u.w;
                }
            }
        }
        __syncthreads();

        // issue NEXT chunk's global loads (latency hides under compute)
        if (cch + 1 < II / KC) {
            const int k0n = (cch + 1) * KC;
            aReg[0].f = *(const float4*)&x[(size_t)(row0 + rA0) * II + k0n + 4 * qA0];
            if (tid < 120)
                aReg[1].f = *(const float4*)&x[(size_t)(row0 + rA1) * II + k0n + 4 * qA1];
            if (tid < HH) {
                const float* wrow = &Wih[(size_t)(c0 + tid) * II + k0n];
                #pragma unroll
                for (int q = 0; q < 5; ++q) bReg[q].f = *(const float4*)&wrow[4 * q];
            }
        }

        // compute chunk cch from smem
        #pragma unroll 4
        for (int k = 0; k < KC; ++k) {
            f4u a0, a1, w0;
            a0.f = *(const float4*)&As[k * AS_STRIDE + ty * 8];
            a1.f = *(const float4*)&As[k * AS_STRIDE + ty * 8 + 4];
            w0.f = *(const float4*)&Bs[k * HH + tx * 4];
            float ar[8] = {a0.f.x, a0.f.y, a0.f.z, a0.f.w,
                           a1.f.x, a1.f.y, a1.f.z, a1.f.w};
            #pragma unroll
            for (int r = 0; r < 8; ++r) {
                f2u av; av.f.x = ar[r]; av.f.y = ar[r];
                acc[r][0] = ffma2(av.u, w0.u.x, acc[r][0]);
                acc[r][1] = ffma2(av.u, w0.u.y, acc[r][1]);
            }
        }
    }

    // Epilogue: add bias, scatter rows to g_xg[t][b][col]
    const int col = c0 + tx * 4;
    f4u bi, bh;
    bi.f = *(const float4*)&bih[col];
    bh.f = *(const float4*)&bhh[col];
    float4 bias = make_float4(bi.f.x + bh.f.x, bi.f.y + bh.f.y,
                              bi.f.z + bh.f.z, bi.f.w + bh.f.w);

    #pragma unroll
    for (int r = 0; r < 8; ++r) {
        int m = row0 + ty * 8 + r;
        int b = m >> 11;           // m / 2048
        int t = m & 2047;
        f2u p0, p1;
        p0.u = acc[r][0]; p1.u = acc[r][1];
        float4 o = make_float4(p0.f.x + bias.x, p0.f.y + bias.y,
                               p1.f.x + bias.z, p1.f.y + bias.w);
        *(float4*)&g_xg[((size_t)t * BB + b) * G4 + col] = o;
    }
}

// ---- kernel 2: sequential LSTM scan (R6 — best measured) ----------------
// One CTA per batch row, 400 threads. Threads 4j..4j+3 own the i,f,g,o
// gates of hidden unit j (same quad) -> combine via quad shfl.
// h double-buffered (1 barrier/step). xg prefetched a FULL GROUP (4 steps)
// ahead via a register ring.
#define SG 4   // steps per prefetch group (TT % SG == 0)

__global__ __launch_bounds__(400, 1)
void scan_kernel(const float* __restrict__ Whh, float* __restrict__ out) {
    const int b    = blockIdx.x;
    const int tid  = threadIdx.x;
    const int j    = tid >> 2;     // hidden unit 0..99
    const int g    = tid & 3;      // gate: 0=i 1=f 2=g 3=o
    const unsigned qmask = 0xFu << ((tid & 31) & ~3);   // this thread's quad

    __shared__ __align__(16) float h_sh[2][HH];

    // W_hh row (g*100 + j), 100 floats -> 25 float4 in registers
    f4u wreg[HH / 4];
    const float4* wr = (const float4*)(Whh + (size_t)(g * HH + j) * HH);
    #pragma unroll
    for (int q = 0; q < HH / 4; ++q) wreg[q].f = wr[q];

    float c = 0.0f, hval = 0.0f;
    if (tid < HH) h_sh[0][tid] = 0.0f;
    __syncthreads();

    const float* xg = g_xg + (size_t)b * G4 + (g * HH + j);
    const size_t tstride = (size_t)BB * G4;

    float cur[SG], nxt[SG];
    #pragma unroll
    for (int i = 0; i < SG; ++i) cur[i] = __ldcs(&xg[(size_t)i * tstride]);

    int p = 0;
    for (int tg = 0; tg < TT; tg += SG) {
        // issue next group's loads NOW (consumed >= SG steps from now)
        #pragma unroll
        for (int i = 0; i < SG; ++i) {
            int tt = tg + SG + i;
            tt = (tt < TT) ? tt : (TT - 1);
            nxt[i] = __ldcs(&xg[(size_t)tt * tstride]);
        }

        #pragma unroll
        for (int i = 0; i < SG; ++i) {
            // 4 independent accumulation chains (depth ~13 each)
            unsigned long long a0 = 0ULL, a1 = 0ULL, a2 = 0ULL, a3 = 0ULL;
            const float4* hb = (const float4*)h_sh[p];
            #pragma unroll
            for (int q = 0; q < HH / 4; ++q) {
                f4u h4; h4.f = hb[q];            // broadcast LDS.128
                if (q & 1) {
                    a2 = ffma2(wreg[q].u.x, h4.u.x, a2);
                    a3 = ffma2(wreg[q].u.y, h4.u.y, a3);
                } else {
                    a0 = ffma2(wreg[q].u.x, h4.u.x, a0);
                    a1 = ffma2(wreg[q].u.y, h4.u.y, a1);
                }
            }
            f2u s0, s1;
            s0.u = fadd2(a0, a2);
            s1.u = fadd2(a1, a3);
            float gate = (s0.f.x + s0.f.y) + (s1.f.x + s1.f.y) + cur[i];

            // branch-free activation: g==2 -> tanh = 2*sig(2x)-1, else sigmoid
            bool is_t = (g == 2);
            float xx = is_t ? 2.0f * gate : gate;
            float s  = __fdividef(1.0f, 1.0f + __expf(-xx));
            float a  = is_t ? fmaf(2.0f, s, -1.0f) : s;

            // quad combine (lanes of this quad, all converged)
            float fg = __shfl_down_sync(qmask, a, 1, 4);
            float gg = __shfl_down_sync(qmask, a, 2, 4);
            float og = __shfl_down_sync(qmask, a, 3, 4);
            if (g == 0) {
                c    = fg * c + a * gg;
                hval = og * tanh_(c);
                h_sh[p ^ 1][j] = hval;           // write OTHER buffer
            }
            __syncthreads();
            p ^= 1;
        }

        #pragma unroll
        for (int i = 0; i < SG; ++i) cur[i] = nxt[i];
    }

    if (g == 0) out[b * HH + j] = hval;
}

// ---- launch ------------------------------------------------------------
extern "C" void kernel_launch(void* const* d_in, const int* in_sizes, int n_in,
                              void* d_out, int out_size) {
    const float* x   = (const float*)d_in[0];   // [64,2048,200]
    const float* Wih = (const float*)d_in[1];   // [400,200]
    const float* Whh = (const float*)d_in[2];   // [400,100]
    const float* bih = (const float*)d_in[3];   // [400]
    const float* bhh = (const float*)d_in[4];   // [400]
    float* out = (float*)d_out;                 // [64,100]

    proj_kernel<<<dim3(TT * BB / 64, 4), 200>>>(x, Wih, bih, bhh);
    scan_kernel<<<BB, 400>>>(Whh, out);
}

// round 15
// speedup vs baseline: 1.2267x; 1.0430x over previous
#include <cuda_runtime.h>
#include <cstdint>

// Problem constants
#define BB   64
#define TT   2048
#define II   200
#define HH   100
#define G4   400   // 4*H

// Scratch: xg[t][b][j] (t-major so scan CTA b streams coalesced rows), ~210MB.
__device__ float g_xg[(size_t)TT * BB * G4];

// ---- packed fp32x2 helpers ---------------------------------------------
union f2u { float2 f; unsigned long long u; };
union f4u { float4 f; ulonglong2 u; };

__device__ __forceinline__ unsigned long long ffma2(unsigned long long a,
                                                    unsigned long long b,
                                                    unsigned long long c) {
    unsigned long long d;
    asm("fma.rn.f32x2 %0, %1, %2, %3;" : "=l"(d) : "l"(a), "l"(b), "l"(c));
    return d;
}
__device__ __forceinline__ unsigned long long fadd2(unsigned long long a,
                                                    unsigned long long b) {
    unsigned long long d;
    asm("add.rn.f32x2 %0, %1, %2;" : "=l"(d) : "l"(a), "l"(b));
    return d;
}
__device__ __forceinline__ float tanh_(float x) {
    return __fdividef(2.0f, 1.0f + __expf(-2.0f * x)) - 1.0f;
}

// ---- kernel 1: input projection (row-packed register GEMM) --------------
// C[131072, 400] = x[131072, 200] @ W_ih^T  (+bias) -> g_xg[t][b][col]
// CTA tile: 128 rows x 100 cols (grid 1024 x 4). 200 threads, occupancy 3.
// Thread tile: 16 rows (8 packed row-pairs) x 4 cols; accumulators are
// f32x2 packed over ROWS, so the packed multiplier pairs come straight
// from the As float4 loads (no unpacking MOVs); only the 4 column weights
// need lane-duplication. Per k: 5 LDS.128 + ~6 MOV + 32 FFMA2.
#define KC   20
#define PROW 128
#define ASTR 132   // padded row stride (floats); 132*4=528B, 16B aligned

__global__ __launch_bounds__(200, 3)
void proj_kernel(const float* __restrict__ x,
                 const float* __restrict__ Wih,
                 const float* __restrict__ bih,
                 const float* __restrict__ bhh) {
    __shared__ float As[KC * ASTR];   // As[k][r], 10.56 KB
    __shared__ float Bs[KC * HH];     // Bs[k][jc], 8 KB

    const int tid  = threadIdx.x;
    const int tx   = tid % 25;            // col group: cols tx*4 .. tx*4+3
    const int ty   = tid / 25;            // row group: rows ty*16 .. ty*16+15
    const int row0 = blockIdx.x * PROW;   // 128-row tile (within one batch)
    const int c0   = blockIdx.y * HH;     // global column base (0/100/200/300)

    unsigned long long acc[8][4];         // [row-pair][col], packed over rows
    #pragma unroll
    for (int p = 0; p < 8; ++p)
        #pragma unroll
        for (int c = 0; c < 4; ++c) acc[p][c] = 0ULL;

    for (int cch = 0; cch < II / KC; ++cch) {
        const int k0 = cch * KC;
        __syncthreads();   // previous chunk fully consumed

        // Stage A: 128 rows x 20 k (640 float4), transposed to As[k][r]
        #pragma unroll
        for (int e = 0; e < 4; ++e) {
            int idx = tid + 200 * e;
            if (idx < PROW * (KC / 4)) {
                int r = idx / (KC / 4);
                int q = idx - r * (KC / 4);
                float4 v = *(const float4*)&x[(size_t)(row0 + r) * II + k0 + 4 * q];
                As[(4 * q + 0) * ASTR + r] = v.x;
                As[(4 * q + 1) * ASTR + r] = v.y;
                As[(4 * q + 2) * ASTR + r] = v.z;
                As[(4 * q + 3) * ASTR + r] = v.w;
            }
        }
        // Stage B (transposing): thread t<100 owns W_ih row c0+t (L2-resident)
        if (tid < HH) {
            const float* wrow = &Wih[(size_t)(c0 + tid) * II + k0];
            #pragma unroll
            for (int q = 0; q < KC / 4; ++q) {
                float4 v = *(const float4*)&wrow[4 * q];
                Bs[(4 * q + 0) * HH + tid] = v.x;
                Bs[(4 * q + 1) * HH + tid] = v.y;
                Bs[(4 * q + 2) * HH + tid] = v.z;
                Bs[(4 * q + 3) * HH + tid] = v.w;
            }
        }
        __syncthreads();

        #pragma unroll 4
        for (int k = 0; k < KC; ++k) {
            f4u a0, a1, a2, a3, w;
            const float* ab = &As[k * ASTR + ty * 16];
            a0.f = *(const float4*)(ab + 0);    // rows +0..3  -> pairs 0,1
            a1.f = *(const float4*)(ab + 4);    // rows +4..7  -> pairs 2,3
            a2.f = *(const float4*)(ab + 8);    // rows +8..11 -> pairs 4,5
            a3.f = *(const float4*)(ab + 12);   // rows +12..15-> pairs 6,7
            w.f  = *(const float4*)&Bs[k * HH + tx * 4];

            unsigned long long wp[4];
            { f2u t0; t0.f.x = w.f.x; t0.f.y = w.f.x; wp[0] = t0.u; }
            { f2u t1; t1.f.x = w.f.y; t1.f.y = w.f.y; wp[1] = t1.u; }
            { f2u t2; t2.f.x = w.f.z; t2.f.y = w.f.z; wp[2] = t2.u; }
            { f2u t3; t3.f.x = w.f.w; t3.f.y = w.f.w; wp[3] = t3.u; }

            unsigned long long ap[8] = {a0.u.x, a0.u.y, a1.u.x, a1.u.y,
                                        a2.u.x, a2.u.y, a3.u.x, a3.u.y};
            #pragma unroll
            for (int p = 0; p < 8; ++p) {
                acc[p][0] = ffma2(ap[p], wp[0], acc[p][0]);
                acc[p][1] = ffma2(ap[p], wp[1], acc[p][1]);
                acc[p][2] = ffma2(ap[p], wp[2], acc[p][2]);
                acc[p][3] = ffma2(ap[p], wp[3], acc[p][3]);
            }
        }
    }

    // Epilogue: add bias, scatter row-pairs to g_xg[t][b][col]
    const int col = c0 + tx * 4;
    f4u bi, bh;
    bi.f = *(const float4*)&bih[col];
    bh.f = *(const float4*)&bhh[col];
    float4 bias = make_float4(bi.f.x + bh.f.x, bi.f.y + bh.f.y,
                              bi.f.z + bh.f.z, bi.f.w + bh.f.w);

    #pragma unroll
    for (int p = 0; p < 8; ++p) {
        f2u u0, u1, u2, u3;
        u0.u = acc[p][0]; u1.u = acc[p][1]; u2.u = acc[p][2]; u3.u = acc[p][3];
        int m0 = row0 + ty * 16 + 2 * p;       // first row of the pair
        int b0 = m0 >> 11, t0 = m0 & 2047;
        float4 o0 = make_float4(u0.f.x + bias.x, u1.f.x + bias.y,
                                u2.f.x + bias.z, u3.f.x + bias.w);
        *(float4*)&g_xg[((size_t)t0 * BB + b0) * G4 + col] = o0;
        int m1 = m0 + 1;
        int b1 = m1 >> 11, t1 = m1 & 2047;
        float4 o1 = make_float4(u0.f.y + bias.x, u1.f.y + bias.y,
                                u2.f.y + bias.z, u3.f.y + bias.w);
        *(float4*)&g_xg[((size_t)t1 * BB + b1) * G4 + col] = o1;
    }
}

// ---- kernel 2: sequential LSTM scan (R6 — best measured, unchanged) -----
// One CTA per batch row, 400 threads. Threads 4j..4j+3 own the i,f,g,o
// gates of hidden unit j (same quad) -> combine via quad shfl.
// h double-buffered (1 barrier/step). xg prefetched a FULL GROUP (4 steps)
// ahead via a register ring.
#define SG 4   // steps per prefetch group (TT % SG == 0)

__global__ __launch_bounds__(400, 1)
void scan_kernel(const float* __restrict__ Whh, float* __restrict__ out) {
    const int b    = blockIdx.x;
    const int tid  = threadIdx.x;
    const int j    = tid >> 2;     // hidden unit 0..99
    const int g    = tid & 3;      // gate: 0=i 1=f 2=g 3=o
    const unsigned qmask = 0xFu << ((tid & 31) & ~3);   // this thread's quad

    __shared__ __align__(16) float h_sh[2][HH];

    // W_hh row (g*100 + j), 100 floats -> 25 float4 in registers
    f4u wreg[HH / 4];
    const float4* wr = (const float4*)(Whh + (size_t)(g * HH + j) * HH);
    #pragma unroll
    for (int q = 0; q < HH / 4; ++q) wreg[q].f = wr[q];

    float c = 0.0f, hval = 0.0f;
    if (tid < HH) h_sh[0][tid] = 0.0f;
    __syncthreads();

    const float* xg = g_xg + (size_t)b * G4 + (g * HH + j);
    const size_t tstride = (size_t)BB * G4;

    float cur[SG], nxt[SG];
    #pragma unroll
    for (int i = 0; i < SG; ++i) cur[i] = __ldcs(&xg[(size_t)i * tstride]);

    int p = 0;
    for (int tg = 0; tg < TT; tg += SG) {
        // issue next group's loads NOW (consumed >= SG steps from now)
        #pragma unroll
        for (int i = 0; i < SG; ++i) {
            int tt = tg + SG + i;
            tt = (tt < TT) ? tt : (TT - 1);
            nxt[i] = __ldcs(&xg[(size_t)tt * tstride]);
        }

        #pragma unroll
        for (int i = 0; i < SG; ++i) {
            // 4 independent accumulation chains (depth ~13 each)
            unsigned long long a0 = 0ULL, a1 = 0ULL, a2 = 0ULL, a3 = 0ULL;
            const float4* hb = (const float4*)h_sh[p];
            #pragma unroll
            for (int q = 0; q < HH / 4; ++q) {
                f4u h4; h4.f = hb[q];            // broadcast LDS.128
                if (q & 1) {
                    a2 = ffma2(wreg[q].u.x, h4.u.x, a2);
                    a3 = ffma2(wreg[q].u.y, h4.u.y, a3);
                } else {
                    a0 = ffma2(wreg[q].u.x, h4.u.x, a0);
                    a1 = ffma2(wreg[q].u.y, h4.u.y, a1);
                }
            }
            f2u s0, s1;
            s0.u = fadd2(a0, a2);
            s1.u = fadd2(a1, a3);
            float gate = (s0.f.x + s0.f.y) + (s1.f.x + s1.f.y) + cur[i];

            // branch-free activation: g==2 -> tanh = 2*sig(2x)-1, else sigmoid
            bool is_t = (g == 2);
            float xx = is_t ? 2.0f * gate : gate;
            float s  = __fdividef(1.0f, 1.0f + __expf(-xx));
            float a  = is_t ? fmaf(2.0f, s, -1.0f) : s;

            // quad combine (lanes of this quad, all converged)
            float fg = __shfl_down_sync(qmask, a, 1, 4);
            float gg = __shfl_down_sync(qmask, a, 2, 4);
            float og = __shfl_down_sync(qmask, a, 3, 4);
            if (g == 0) {
                c    = fg * c + a * gg;
                hval = og * tanh_(c);
                h_sh[p ^ 1][j] = hval;           // write OTHER buffer
            }
            __syncthreads();
            p ^= 1;
        }

        #pragma unroll
        for (int i = 0; i < SG; ++i) cur[i] = nxt[i];
    }

    if (g == 0) out[b * HH + j] = hval;
}

// ---- launch ------------------------------------------------------------
extern "C" void kernel_launch(void* const* d_in, const int* in_sizes, int n_in,
                              void* d_out, int out_size) {
    const float* x   = (const float*)d_in[0];   // [64,2048,200]
    const float* Wih = (const float*)d_in[1];   // [400,200]
    const float* Whh = (const float*)d_in[2];   // [400,100]
    const float* bih = (const float*)d_in[3];   // [400]
    const float* bhh = (const float*)d_in[4];   // [400]
    float* out = (float*)d_out;                 // [64,100]

    proj_kernel<<<dim3(TT * BB / PROW, 4), 200>>>(x, Wih, bih, bhh);
    scan_kernel<<<BB, 400>>>(Whh, out);
}